// round 3
// baseline (speedup 1.0000x reference)
#include <cuda_runtime.h>
#include <math.h>

// Problem constants (fixed by setup_inputs)
#define HID   64
#define NPT   128
#define LBF   (-5.0f)
#define BPB   8      // batches per block

__device__ __forceinline__ unsigned f2tf32(float x) {
    unsigned r;
    asm("cvt.rna.tf32.f32 %0, %1;\n" : "=r"(r) : "f"(x));
    return r;
}

__device__ __forceinline__ void mma_tf32(float c[4],
                                         unsigned a0, unsigned a1, unsigned a2, unsigned a3,
                                         unsigned b0, unsigned b1) {
    asm volatile(
        "mma.sync.aligned.m16n8k8.row.col.f32.tf32.tf32.f32 "
        "{%0,%1,%2,%3}, {%4,%5,%6,%7}, {%8,%9}, {%0,%1,%2,%3};\n"
        : "+f"(c[0]), "+f"(c[1]), "+f"(c[2]), "+f"(c[3])
        : "r"(a0), "r"(a1), "r"(a2), "r"(a3), "r"(b0), "r"(b1));
}

// LeakyReLU(0.01) == max(h, 0.01h)
__device__ __forceinline__ float lrelu(float h) { return fmaxf(h, 0.01f * h); }

__global__ __launch_bounds__(256, 2)
void mono_mlp_tc2_kernel(const float* __restrict__ z,  const float* __restrict__ u,
                         const float* __restrict__ w01, const float* __restrict__ b01,
                         const float* __restrict__ w02, const float* __restrict__ b02,
                         const float* __restrict__ w03, const float* __restrict__ b03,
                         const float* __restrict__ w11, const float* __restrict__ b11,
                         const float* __restrict__ w12, const float* __restrict__ b12,
                         const float* __restrict__ w13, const float* __restrict__ b13,
                         const float* __restrict__ bias, float* __restrict__ out, int B)
{
    // B fragments (tf32, mma order): bfrag[((d*8+kt)*8+nt)*32 + lane]
    __shared__ uint2  bfrag[2 * 8 * 8 * 32];   // 32 KB
    __shared__ float2 w3b2[2][HID];            // (w3[j], b2[j])
    __shared__ float  b3s[2];
    __shared__ float  sred[2][NPT];            // per-point partial sums, 2 n-halves
    __shared__ float  red4[4];
    __shared__ float  hzacc[BPB];

    const int tid = threadIdx.x;

    // ---- Build weight structures (once per block) ----
    for (int e = tid; e < 2 * 8 * 8 * 32; e += 256) {
        const int lane = e & 31;
        const int nt   = (e >> 5) & 7;
        const int kt   = (e >> 8) & 7;
        const int d    = (e >> 11) & 1;
        const int n    = 8 * nt + (lane >> 2);
        const int k    = 8 * kt + (lane & 3);
        const float* w2 = d ? w12 : w02;
        bfrag[e] = make_uint2(f2tf32(w2[n * 64 + k]), f2tf32(w2[n * 64 + k + 4]));
    }
    if (tid < HID) {
        w3b2[0][tid] = make_float2(w03[tid], b02[tid]);
        w3b2[1][tid] = make_float2(w13[tid], b12[tid]);
    }
    if (tid == 0) { b3s[0] = b03[0]; b3s[1] = b13[0]; }
    if (tid < BPB) hzacc[tid] = bias[0];
    __syncthreads();

    const int warp  = tid >> 5;
    const int lane  = tid & 31;
    const int gid   = lane >> 2;       // row-group within m16
    const int tig   = lane & 3;        // k / col selector
    const int phalf = warp >> 1;       // point range: 32*phalf .. +31
    const int nhalf = warp & 1;        // n-column half: 32*nhalf .. +31
    const int pbase = 32 * phalf;
    const int nbase = 32 * nhalf;

    // this thread's 4 point rows (2 pt-tiles x 2 rows)
    const int p00 = pbase + gid;       // pt0 row0   (<= 103)
    const int p01 = p00 + 8;           // pt0 row1   (<= 111)
    const int p10 = p00 + 16;          // pt1 row0   (<= 119)
    const int p11 = p00 + 24;          // pt1 row1   (<= 127)

    #pragma unroll 1
    for (int d = 0; d < 2; d++) {
        // layer-1 weights for this thread's k columns, in registers
        const float* w1 = d ? w11 : w01;
        const float* bb = d ? b11 : b01;
        float2 wka[8], wkb[8];
        #pragma unroll
        for (int kt = 0; kt < 8; kt++) {
            wka[kt] = make_float2(w1[8 * kt + tig],     bb[8 * kt + tig]);
            wkb[kt] = make_float2(w1[8 * kt + tig + 4], bb[8 * kt + tig + 4]);
        }
        const float b3v = b3s[d];

        #pragma unroll 1
        for (int bi = 0; bi < BPB; bi++) {
            const int b = blockIdx.x * BPB + bi;
            if (b >= B) break;

            const float zc  = fmaxf(z[b * 2 + d], LBF);
            const float dsz = (zc - LBF) * (1.0f / (float)(NPT - 1));
            const int   ub  = (b * 2 + d) * (NPT - 1);

            // layer-0 inputs x at the 4 point rows
            const float u3 = (p11 < NPT - 1) ? u[ub + p11] : 0.0f;
            const float x00 = fmaf(dsz, (float)p00 + u[ub + p00], LBF);
            const float x01 = fmaf(dsz, (float)p01 + u[ub + p01], LBF);
            const float x10 = fmaf(dsz, (float)p10 + u[ub + p10], LBF);
            const float x11 = fmaf(dsz, (float)p11 + u3,          LBF);

            // ---- layer-2 GEMM: 32 points x 32 n-cols per warp, K=64 ----
            float acc[2][4][4];
            #pragma unroll
            for (int pt = 0; pt < 2; pt++)
                #pragma unroll
                for (int nt = 0; nt < 4; nt++)
                    #pragma unroll
                    for (int q = 0; q < 4; q++) acc[pt][nt][q] = 0.0f;

            const uint2* bbase = &bfrag[(d * 64) * 32 + (4 * nhalf) * 32 + lane];

            #pragma unroll
            for (int kt = 0; kt < 8; kt++) {
                const uint2* bp = bbase + (kt * 8) * 32;
                const uint2 bf0 = bp[0];
                const uint2 bf1 = bp[32];
                const uint2 bf2 = bp[64];
                const uint2 bf3 = bp[96];

                const float2 wa = wka[kt], wb = wkb[kt];
                // A fragments for 2 pt-tiles (truncation to tf32 happens in HW)
                const unsigned a00 = __float_as_uint(lrelu(fmaf(x00, wa.x, wa.y)));
                const unsigned a01 = __float_as_uint(lrelu(fmaf(x01, wa.x, wa.y)));
                const unsigned a02 = __float_as_uint(lrelu(fmaf(x00, wb.x, wb.y)));
                const unsigned a03 = __float_as_uint(lrelu(fmaf(x01, wb.x, wb.y)));
                const unsigned a10 = __float_as_uint(lrelu(fmaf(x10, wa.x, wa.y)));
                const unsigned a11 = __float_as_uint(lrelu(fmaf(x11, wa.x, wa.y)));
                const unsigned a12 = __float_as_uint(lrelu(fmaf(x10, wb.x, wb.y)));
                const unsigned a13 = __float_as_uint(lrelu(fmaf(x11, wb.x, wb.y)));

                mma_tf32(acc[0][0], a00, a01, a02, a03, bf0.x, bf0.y);
                mma_tf32(acc[0][1], a00, a01, a02, a03, bf1.x, bf1.y);
                mma_tf32(acc[0][2], a00, a01, a02, a03, bf2.x, bf2.y);
                mma_tf32(acc[0][3], a00, a01, a02, a03, bf3.x, bf3.y);
                mma_tf32(acc[1][0], a10, a11, a12, a13, bf0.x, bf0.y);
                mma_tf32(acc[1][1], a10, a11, a12, a13, bf1.x, bf1.y);
                mma_tf32(acc[1][2], a10, a11, a12, a13, bf2.x, bf2.y);
                mma_tf32(acc[1][3], a10, a11, a12, a13, bf3.x, bf3.y);
            }

            // ---- epilogue: bias + LeakyReLU, dot w3 over this warp's 32 n ----
            float s[2][2] = {{0.f, 0.f}, {0.f, 0.f}};   // [pt][row]
            #pragma unroll
            for (int nt = 0; nt < 4; nt++) {
                const int j0 = nbase + 8 * nt + 2 * tig;
                const float2 e0 = w3b2[d][j0];
                const float2 e1 = w3b2[d][j0 + 1];
                #pragma unroll
                for (int pt = 0; pt < 2; pt++) {
                    float h;
                    h = lrelu(acc[pt][nt][0] + e0.y); s[pt][0] = fmaf(h, e0.x, s[pt][0]);
                    h = lrelu(acc[pt][nt][1] + e1.y); s[pt][0] = fmaf(h, e1.x, s[pt][0]);
                    h = lrelu(acc[pt][nt][2] + e0.y); s[pt][1] = fmaf(h, e0.x, s[pt][1]);
                    h = lrelu(acc[pt][nt][3] + e1.y); s[pt][1] = fmaf(h, e1.x, s[pt][1]);
                }
            }
            // fold the tig quad (each point's partial over 32 n-cols)
            #pragma unroll
            for (int pt = 0; pt < 2; pt++)
                #pragma unroll
                for (int r = 0; r < 2; r++) {
                    s[pt][r] += __shfl_xor_sync(0xffffffffu, s[pt][r], 1);
                    s[pt][r] += __shfl_xor_sync(0xffffffffu, s[pt][r], 2);
                }
            if (tig == 0) {
                sred[nhalf][p00] = s[0][0];
                sred[nhalf][p01] = s[0][1];
                sred[nhalf][p10] = s[1][0];
                sred[nhalf][p11] = s[1][1];
            }
            __syncthreads();

            // combine the two n-halves, ELU, block-reduce over 128 points
            if (tid < NPT) {
                const float v = sred[0][tid] + sred[1][tid] + b3v;
                float t = ((v > 0.f) ? v : expm1f(v)) + 1.0f;
                t += __shfl_xor_sync(0xffffffffu, t, 16);
                t += __shfl_xor_sync(0xffffffffu, t, 8);
                t += __shfl_xor_sync(0xffffffffu, t, 4);
                t += __shfl_xor_sync(0xffffffffu, t, 2);
                t += __shfl_xor_sync(0xffffffffu, t, 1);
                if ((tid & 31) == 0) red4[tid >> 5] = t;
            }
            __syncthreads();
            if (tid == 0)
                hzacc[bi] = fmaf(red4[0] + red4[1] + red4[2] + red4[3], dsz, hzacc[bi]);
        }
    }

    __syncthreads();
    if (tid < BPB) {
        const int b = blockIdx.x * BPB + tid;
        if (b < B) out[b] = hzacc[tid];
    }
}

extern "C" void kernel_launch(void* const* d_in, const int* in_sizes, int n_in,
                              void* d_out, int out_size)
{
    const float* z   = (const float*)d_in[0];
    const float* u   = (const float*)d_in[1];
    const float* w01 = (const float*)d_in[2];
    const float* b01 = (const float*)d_in[3];
    const float* w02 = (const float*)d_in[4];
    const float* b02 = (const float*)d_in[5];
    const float* w03 = (const float*)d_in[6];
    const float* b03 = (const float*)d_in[7];
    const float* w11 = (const float*)d_in[8];
    const float* b11 = (const float*)d_in[9];
    const float* w12 = (const float*)d_in[10];
    const float* b12 = (const float*)d_in[11];
    const float* w13 = (const float*)d_in[12];
    const float* b13 = (const float*)d_in[13];
    const float* bias= (const float*)d_in[14];
    float* out = (float*)d_out;

    const int B = in_sizes[0] / 2;
    const int grid = (B + BPB - 1) / BPB;
    mono_mlp_tc2_kernel<<<grid, 256>>>(
        z, u, w01, b01, w02, b02, w03, b03,
        w11, b11, w12, b12, w13, b13, bias, out, B);
}